// round 4
// baseline (speedup 1.0000x reference)
#include <cuda_runtime.h>
#include <math.h>

// ContrastiveLoss: N=4096 (%128==0), D=768 (%16==0, float4-aligned)
// loss = sum_{i<j} [ same ? d2 : max(1-sqrt(d2+eps),0)^2 ] / (N*(N-1)/2)
// d2 = |xi|^2 + |xj|^2 - 2 xi.xj  (clamped at 0)

#define MARGIN 1.0f
#define EPSV   1e-12f

__device__ float g_sq[4096];
__device__ float g_partials[1024];

// --- row squared norms: 8 rows per block, one warp per row ---
__global__ void norm_kernel(const float* __restrict__ X, int n, int d) {
    int row = blockIdx.x * 8 + threadIdx.y;
    if (row >= n) return;
    const float4* xr = (const float4*)(X + (size_t)row * d);
    float s = 0.f;
    int d4 = d >> 2;
    for (int c = threadIdx.x; c < d4; c += 32) {
        float4 v = xr[c];
        s += v.x * v.x + v.y * v.y + v.z * v.z + v.w * v.w;
    }
    #pragma unroll
    for (int o = 16; o > 0; o >>= 1) s += __shfl_down_sync(0xffffffffu, s, o);
    if (threadIdx.x == 0) g_sq[row] = s;
}

// --- fused Gram tile + contrastive epilogue ---
// 128x128 tile, BK=16, 256 threads, 8x8 per-thread microtile, reg-prefetched.
__global__ void __launch_bounds__(256, 2) tile_kernel(
    const float* __restrict__ X, const int* __restrict__ lab, int d, int nb)
{
    const int bi = blockIdx.y;
    const int bj = blockIdx.x;
    if (bj < bi) return;

    __shared__ float As[16][132];   // A^T: As[k][m]
    __shared__ float Bs[16][132];
    __shared__ float sqA[128], sqB[128];
    __shared__ int   labA[128], labB[128];
    __shared__ float red[256];

    const int tid = threadIdx.x;
    const int tx = tid & 15;        // 0..15 -> 8 cols each
    const int ty = tid >> 4;        // 0..15 -> 8 rows each
    const int rbase = bi * 128;
    const int cbase = bj * 128;

    if (tid < 128) {
        sqA[tid] = g_sq[rbase + tid];
        labA[tid] = lab[rbase + tid];
    } else {
        int t = tid - 128;
        sqB[t] = g_sq[cbase + t];
        labB[t] = lab[cbase + t];
    }

    // per-thread load coords (2 float4 per matrix per tile)
    const int row0 = (tid + 0)   >> 2;  // 0..63
    const int row1 = (tid + 256) >> 2;  // 64..127
    const int c4   = (tid & 3) * 4;     // column offset within 16

    const float* pA0 = X + (size_t)(rbase + row0) * d + c4;
    const float* pA1 = X + (size_t)(rbase + row1) * d + c4;
    const float* pB0 = X + (size_t)(cbase + row0) * d + c4;
    const float* pB1 = X + (size_t)(cbase + row1) * d + c4;

    float acc[8][8];
    #pragma unroll
    for (int i = 0; i < 8; i++)
        #pragma unroll
        for (int j = 0; j < 8; j++) acc[i][j] = 0.f;

    // prefetch tile 0
    float4 ra0 = *(const float4*)(pA0);
    float4 ra1 = *(const float4*)(pA1);
    float4 rb0 = *(const float4*)(pB0);
    float4 rb1 = *(const float4*)(pB1);

    for (int k0 = 0; k0 < d; k0 += 16) {
        // store current tile (smem transposed)
        As[c4 + 0][row0] = ra0.x; As[c4 + 1][row0] = ra0.y;
        As[c4 + 2][row0] = ra0.z; As[c4 + 3][row0] = ra0.w;
        As[c4 + 0][row1] = ra1.x; As[c4 + 1][row1] = ra1.y;
        As[c4 + 2][row1] = ra1.z; As[c4 + 3][row1] = ra1.w;
        Bs[c4 + 0][row0] = rb0.x; Bs[c4 + 1][row0] = rb0.y;
        Bs[c4 + 2][row0] = rb0.z; Bs[c4 + 3][row0] = rb0.w;
        Bs[c4 + 0][row1] = rb1.x; Bs[c4 + 1][row1] = rb1.y;
        Bs[c4 + 2][row1] = rb1.z; Bs[c4 + 3][row1] = rb1.w;
        __syncthreads();

        // prefetch next tile (overlaps the FMA burst below)
        if (k0 + 16 < d) {
            int off = k0 + 16;
            ra0 = *(const float4*)(pA0 + off);
            ra1 = *(const float4*)(pA1 + off);
            rb0 = *(const float4*)(pB0 + off);
            rb1 = *(const float4*)(pB1 + off);
        }

        #pragma unroll
        for (int k = 0; k < 16; k++) {
            float a[8], b[8];
            #pragma unroll
            for (int i = 0; i < 8; i++) a[i] = As[k][ty * 8 + i];
            #pragma unroll
            for (int j = 0; j < 8; j++) b[j] = Bs[k][tx * 8 + j];
            #pragma unroll
            for (int i = 0; i < 8; i++)
                #pragma unroll
                for (int j = 0; j < 8; j++)
                    acc[i][j] = fmaf(a[i], b[j], acc[i][j]);
        }
        __syncthreads();
    }

    // epilogue: fused contrastive pair loss over this thread's 8x8 outputs
    float lsum = 0.f;
    const int mi0 = ty * 8;
    const int nj0 = tx * 8;
    #pragma unroll
    for (int i = 0; i < 8; i++) {
        int gi = rbase + mi0 + i;
        float sqi = sqA[mi0 + i];
        int li = labA[mi0 + i];
        #pragma unroll
        for (int j = 0; j < 8; j++) {
            int gj = cbase + nj0 + j;
            if (gi < gj) {
                float d2 = fmaxf(sqi + sqB[nj0 + j] - 2.f * acc[i][j], 0.f);
                if (li == labB[nj0 + j]) {
                    lsum += d2;
                } else {
                    float h = fmaxf(MARGIN - sqrtf(d2 + EPSV), 0.f);
                    lsum += h * h;
                }
            }
        }
    }

    // deterministic block reduction
    red[tid] = lsum;
    __syncthreads();
    #pragma unroll
    for (int s = 128; s > 0; s >>= 1) {
        if (tid < s) red[tid] += red[tid + s];
        __syncthreads();
    }
    if (tid == 0) {
        int slot = bi * nb - (bi * (bi - 1)) / 2 + (bj - bi);
        g_partials[slot] = red[0];
    }
}

// --- deterministic final reduction + scale ---
__global__ void final_kernel(float* out, int nblocks, float inv_count) {
    __shared__ float red[256];
    int tid = threadIdx.x;
    float s = 0.f;
    for (int i = tid; i < nblocks; i += 256) s += g_partials[i];
    red[tid] = s;
    __syncthreads();
    #pragma unroll
    for (int k = 128; k > 0; k >>= 1) {
        if (tid < k) red[tid] += red[tid + k];
        __syncthreads();
    }
    if (tid == 0) out[0] = red[0] * inv_count;
}

extern "C" void kernel_launch(void* const* d_in, const int* in_sizes, int n_in,
                              void* d_out, int out_size) {
    const float* X  = (const float*)d_in[0];
    const int* lab  = (const int*)d_in[1];
    int n = in_sizes[1];            // 4096
    int d = in_sizes[0] / n;        // 768
    int nb = n / 128;               // 32

    norm_kernel<<<(n + 7) / 8, dim3(32, 8)>>>(X, n, d);

    dim3 grid(nb, nb);
    tile_kernel<<<grid, 256>>>(X, lab, d, nb);

    double cnt = (double)n * (double)(n - 1) * 0.5;
    int ntri = nb * (nb + 1) / 2;
    final_kernel<<<1, 256>>>((float*)d_out, ntri, (float)(1.0 / cnt));
}

// round 10
// speedup vs baseline: 3.8994x; 3.8994x over previous
#include <cuda_runtime.h>
#include <cuda_bf16.h>
#include <math.h>
#include <stdint.h>

// ContrastiveLoss N=4096, D=768. loss = mean_{i<j} [same ? d2 : hinge^2]
// d2 = |xi|^2+|xj|^2-2 xi.xj ; Gram in bf16 mma.sync, norms exact fp32.

#define MARGIN 1.0f
#define EPSV   1e-12f

__device__ float g_sq[4096];
__device__ float g_partials[1024];
__device__ __nv_bfloat16 g_hi[4096 * 768];   // bf16 copy of X

#define LDS 40   // bf16 elements per smem row (32 data + 8 pad), 80B stride

__device__ __forceinline__ uint32_t smem_cast(const void* p) {
    return (uint32_t)__cvta_generic_to_shared(p);
}
#define CP_ASYNC16(dst, src) \
    asm volatile("cp.async.cg.shared.global [%0], [%1], 16;\n" :: "r"(dst), "l"(src))
#define CP_COMMIT() asm volatile("cp.async.commit_group;\n" ::: "memory")
#define CP_WAIT1()  asm volatile("cp.async.wait_group 1;\n" ::: "memory")
#define CP_WAIT0()  asm volatile("cp.async.wait_group 0;\n" ::: "memory")

__device__ __forceinline__ void ldmx4(uint32_t* r, uint32_t addr) {
    asm volatile("ldmatrix.sync.aligned.m8n8.x4.shared.b16 {%0,%1,%2,%3}, [%4];\n"
                 : "=r"(r[0]), "=r"(r[1]), "=r"(r[2]), "=r"(r[3]) : "r"(addr));
}
__device__ __forceinline__ void mma16816(float* c, const uint32_t* a,
                                         uint32_t b0, uint32_t b1) {
    asm volatile(
        "mma.sync.aligned.m16n8k16.row.col.f32.bf16.bf16.f32 "
        "{%0,%1,%2,%3}, {%4,%5,%6,%7}, {%8,%9}, {%0,%1,%2,%3};\n"
        : "+f"(c[0]), "+f"(c[1]), "+f"(c[2]), "+f"(c[3])
        : "r"(a[0]), "r"(a[1]), "r"(a[2]), "r"(a[3]), "r"(b0), "r"(b1));
}

// ---------------- kernel 1: convert f32 -> bf16 + row norms ----------------
__global__ void conv_kernel(const float* __restrict__ X, int n, int d) {
    int row = blockIdx.x * 8 + threadIdx.y;
    if (row >= n) return;
    const float4* xr = (const float4*)(X + (size_t)row * d);
    __nv_bfloat162* hr = (__nv_bfloat162*)(g_hi + (size_t)row * d);
    float s = 0.f;
    int d4 = d >> 2;
    for (int c = threadIdx.x; c < d4; c += 32) {
        float4 v = xr[c];
        s += v.x * v.x + v.y * v.y + v.z * v.z + v.w * v.w;
        hr[2 * c + 0] = __nv_bfloat162(__float2bfloat16_rn(v.x), __float2bfloat16_rn(v.y));
        hr[2 * c + 1] = __nv_bfloat162(__float2bfloat16_rn(v.z), __float2bfloat16_rn(v.w));
    }
    #pragma unroll
    for (int o = 16; o > 0; o >>= 1) s += __shfl_down_sync(0xffffffffu, s, o);
    if (threadIdx.x == 0) g_sq[row] = s;
}

// ---------------- kernel 2: mma.sync Gram tile + fused epilogue ----------------
// 128x128 tile, 256 threads = 8 warps in 4(M) x 2(N); warp tile 32x64.
// KC=32 per double-buffered stage, cp.async fed.
__global__ void __launch_bounds__(256) tile_kernel(
    const int* __restrict__ lab, int d, int nb)
{
    const int bi = blockIdx.y;
    const int bj = blockIdx.x;
    if (bj < bi) return;

    __shared__ __align__(16) __nv_bfloat16 sA[2][128 * LDS];
    __shared__ __align__(16) __nv_bfloat16 sB[2][128 * LDS];
    __shared__ float sqA[128], sqB[128];
    __shared__ int   labA[128], labB[128];
    __shared__ float red[256];

    const int tid = threadIdx.x;
    const int wid = tid >> 5;
    const int lid = tid & 31;
    const int rbase = bi * 128;
    const int cbase = bj * 128;

    if (tid < 128) {
        sqA[tid] = g_sq[rbase + tid];
        labA[tid] = lab[rbase + tid];
    } else {
        int t = tid - 128;
        sqB[t] = g_sq[cbase + t];
        labB[t] = lab[cbase + t];
    }

    // global->smem coords: 2 x 16B vectors per matrix per stage per thread
    const int v0 = tid;            // 0..255
    const int v1 = tid + 256;      // 256..511
    const int gr0 = v0 >> 2, gc0 = (v0 & 3) * 8;   // row, elem offset
    const int gr1 = v1 >> 2, gc1 = (v1 & 3) * 8;
    const __nv_bfloat16* Arow = g_hi + (size_t)rbase * d;
    const __nv_bfloat16* Brow = g_hi + (size_t)cbase * d;

    const int NC = d / 32;   // 24 stages

    // issue stage 0
    {
        CP_ASYNC16(smem_cast(&sA[0][gr0 * LDS + gc0]), Arow + (size_t)gr0 * d + gc0);
        CP_ASYNC16(smem_cast(&sA[0][gr1 * LDS + gc1]), Arow + (size_t)gr1 * d + gc1);
        CP_ASYNC16(smem_cast(&sB[0][gr0 * LDS + gc0]), Brow + (size_t)gr0 * d + gc0);
        CP_ASYNC16(smem_cast(&sB[0][gr1 * LDS + gc1]), Brow + (size_t)gr1 * d + gc1);
        CP_COMMIT();
    }

    // warp tile coords
    const int wm = (wid & 3) * 32;
    const int wn = (wid >> 2) * 64;
    const int lrow  = lid & 15;
    const int lcol8 = (lid >> 4) * 8;

    float acc[2][8][4];
    #pragma unroll
    for (int am = 0; am < 2; am++)
        #pragma unroll
        for (int an = 0; an < 8; an++)
            #pragma unroll
            for (int r = 0; r < 4; r++) acc[am][an][r] = 0.f;

    for (int c = 0; c < NC; c++) {
        const int s = c & 1;
        // issue next stage
        if (c + 1 < NC) {
            const int ns = s ^ 1;
            const int k0 = (c + 1) * 32;
            CP_ASYNC16(smem_cast(&sA[ns][gr0 * LDS + gc0]), Arow + (size_t)gr0 * d + k0 + gc0);
            CP_ASYNC16(smem_cast(&sA[ns][gr1 * LDS + gc1]), Arow + (size_t)gr1 * d + k0 + gc1);
            CP_ASYNC16(smem_cast(&sB[ns][gr0 * LDS + gc0]), Brow + (size_t)gr0 * d + k0 + gc0);
            CP_ASYNC16(smem_cast(&sB[ns][gr1 * LDS + gc1]), Brow + (size_t)gr1 * d + k0 + gc1);
            CP_COMMIT();
            CP_WAIT1();     // stage c done, stage c+1 may be in flight
        } else {
            CP_WAIT0();
        }
        __syncthreads();

        #pragma unroll
        for (int ks = 0; ks < 2; ks++) {
            uint32_t afr[2][4];
            #pragma unroll
            for (int am = 0; am < 2; am++)
                ldmx4(afr[am], smem_cast(&sA[s][(wm + am * 16 + lrow) * LDS + ks * 16 + lcol8]));
            uint32_t bfr[4][4];
            #pragma unroll
            for (int p = 0; p < 4; p++)
                ldmx4(bfr[p], smem_cast(&sB[s][(wn + p * 16 + lrow) * LDS + ks * 16 + lcol8]));
            #pragma unroll
            for (int am = 0; am < 2; am++)
                #pragma unroll
                for (int an = 0; an < 8; an++) {
                    const int p = an >> 1, h = an & 1;
                    mma16816(acc[am][an], afr[am], bfr[p][h], bfr[p][h + 2]);
                }
        }
        __syncthreads();   // stage s consumed; safe to overwrite next iter
    }

    // fused epilogue on C fragments
    float lsum = 0.f;
    const int r4 = lid >> 2;        // 0..7
    const int c2 = (lid & 3) * 2;   // 0,2,4,6
    #pragma unroll
    for (int am = 0; am < 2; am++) {
        #pragma unroll
        for (int an = 0; an < 8; an++) {
            #pragma unroll
            for (int r = 0; r < 4; r++) {
                const int mi = wm + am * 16 + r4 + ((r & 2) ? 8 : 0);
                const int nj = wn + an * 8 + c2 + (r & 1);
                const int gi = rbase + mi;
                const int gj = cbase + nj;
                if (gi < gj) {
                    float d2 = fmaxf(sqA[mi] + sqB[nj] - 2.f * acc[am][an][r], 0.f);
                    if (labA[mi] == labB[nj]) {
                        lsum += d2;
                    } else {
                        float h = fmaxf(MARGIN - sqrtf(d2 + EPSV), 0.f);
                        lsum += h * h;
                    }
                }
            }
        }
    }

    // deterministic block reduction
    red[tid] = lsum;
    __syncthreads();
    #pragma unroll
    for (int st = 128; st > 0; st >>= 1) {
        if (tid < st) red[tid] += red[tid + st];
        __syncthreads();
    }
    if (tid == 0) {
        int slot = bi * nb - (bi * (bi - 1)) / 2 + (bj - bi);
        g_partials[slot] = red[0];
    }
}

// ---------------- final deterministic reduction ----------------
__global__ void final_kernel(float* out, int nblocks, float inv_count) {
    __shared__ float red[256];
    int tid = threadIdx.x;
    float s = 0.f;
    for (int i = tid; i < nblocks; i += 256) s += g_partials[i];
    red[tid] = s;
    __syncthreads();
    #pragma unroll
    for (int k = 128; k > 0; k >>= 1) {
        if (tid < k) red[tid] += red[tid + k];
        __syncthreads();
    }
    if (tid == 0) out[0] = red[0] * inv_count;
}

extern "C" void kernel_launch(void* const* d_in, const int* in_sizes, int n_in,
                              void* d_out, int out_size) {
    const float* X  = (const float*)d_in[0];
    const int* lab  = (const int*)d_in[1];
    int n = in_sizes[1];            // 4096
    int d = in_sizes[0] / n;        // 768
    int nb = n / 128;               // 32

    conv_kernel<<<(n + 7) / 8, dim3(32, 8)>>>(X, n, d);

    dim3 grid(nb, nb);
    tile_kernel<<<grid, 256>>>(lab, d, nb);

    double cnt = (double)n * (double)(n - 1) * 0.5;
    int ntri = nb * (nb + 1) / 2;
    final_kernel<<<1, 256>>>((float*)d_out, ntri, (float)(1.0 / cnt));
}

// round 12
// speedup vs baseline: 4.1654x; 1.0682x over previous
#include <cuda_runtime.h>
#include <cuda_bf16.h>
#include <math.h>
#include <stdint.h>

// ContrastiveLoss N=4096, D=768. loss = mean_{i<j} [same ? d2 : hinge^2]
// d2 = |xi|^2+|xj|^2-2 xi.xj ; Gram in bf16 mma.sync, norms exact fp32.

#define MARGIN 1.0f
#define EPSV   1e-12f

__device__ float g_sq[4096];
__device__ float g_partials[1024];
__device__ __nv_bfloat16 g_hi[4096 * 768];   // bf16 copy of X

#define LDS 40          // bf16 per smem row (32 data + 8 pad) -> 80B stride, ldmatrix conflict-free
#define STAGES 3
#define STAGE_ELEMS (128 * LDS)          // per matrix per stage
#define STAGE_BYTES (STAGE_ELEMS * 2)    // 10240

__device__ __forceinline__ uint32_t smem_cast(const void* p) {
    return (uint32_t)__cvta_generic_to_shared(p);
}
#define CP_ASYNC16(dst, src) \
    asm volatile("cp.async.cg.shared.global [%0], [%1], 16;\n" :: "r"(dst), "l"(src))
#define CP_COMMIT() asm volatile("cp.async.commit_group;\n" ::: "memory")
#define CP_WAIT1()  asm volatile("cp.async.wait_group 1;\n" ::: "memory")
#define CP_WAIT0()  asm volatile("cp.async.wait_group 0;\n" ::: "memory")

__device__ __forceinline__ void ldmx4(uint32_t* r, uint32_t addr) {
    asm volatile("ldmatrix.sync.aligned.m8n8.x4.shared.b16 {%0,%1,%2,%3}, [%4];\n"
                 : "=r"(r[0]), "=r"(r[1]), "=r"(r[2]), "=r"(r[3]) : "r"(addr));
}
__device__ __forceinline__ void mma16816(float* c, const uint32_t* a,
                                         uint32_t b0, uint32_t b1) {
    asm volatile(
        "mma.sync.aligned.m16n8k16.row.col.f32.bf16.bf16.f32 "
        "{%0,%1,%2,%3}, {%4,%5,%6,%7}, {%8,%9}, {%0,%1,%2,%3};\n"
        : "+f"(c[0]), "+f"(c[1]), "+f"(c[2]), "+f"(c[3])
        : "r"(a[0]), "r"(a[1]), "r"(a[2]), "r"(a[3]), "r"(b0), "r"(b1));
}

// ---------------- kernel 1: convert f32 -> bf16 + row norms ----------------
__global__ void conv_kernel(const float* __restrict__ X, int n, int d) {
    int row = blockIdx.x * 8 + threadIdx.y;
    if (row >= n) return;
    const float4* xr = (const float4*)(X + (size_t)row * d);
    __nv_bfloat162* hr = (__nv_bfloat162*)(g_hi + (size_t)row * d);
    float s = 0.f;
    int d4 = d >> 2;
    #pragma unroll 6
    for (int c = threadIdx.x; c < d4; c += 32) {
        float4 v = xr[c];
        s += v.x * v.x + v.y * v.y + v.z * v.z + v.w * v.w;
        hr[2 * c + 0] = __nv_bfloat162(__float2bfloat16_rn(v.x), __float2bfloat16_rn(v.y));
        hr[2 * c + 1] = __nv_bfloat162(__float2bfloat16_rn(v.z), __float2bfloat16_rn(v.w));
    }
    #pragma unroll
    for (int o = 16; o > 0; o >>= 1) s += __shfl_down_sync(0xffffffffu, s, o);
    if (threadIdx.x == 0) g_sq[row] = s;
}

// ---------------- kernel 2: mma.sync Gram tile + fused epilogue ----------------
// Triangular 1D grid (528 blocks). 128x128 tile, 256 threads = 8 warps 4(M)x2(N),
// warp tile 32x64. KC=32 per stage, 3-stage cp.async pipeline, ONE sync per iter.
__global__ void __launch_bounds__(256, 2) tile_kernel(
    const int* __restrict__ lab, int d, int nb)
{
    // decode upper-triangle block coords from linear slot
    const int slot = blockIdx.x;
    int bi = (int)((2.f * nb + 1.f -
                    sqrtf((2.f * nb + 1.f) * (2.f * nb + 1.f) - 8.f * slot)) * 0.5f);
    while (slot >= (bi + 1) * nb - ((bi + 1) * bi) / 2) bi++;
    while (slot <  bi * nb - (bi * (bi - 1)) / 2)       bi--;
    const int bj = bi + (slot - (bi * nb - (bi * (bi - 1)) / 2));

    extern __shared__ __align__(16) __nv_bfloat16 dyn[];
    __nv_bfloat16* sAbuf = dyn;                          // STAGES * STAGE_ELEMS
    __nv_bfloat16* sBbuf = dyn + STAGES * STAGE_ELEMS;   // STAGES * STAGE_ELEMS
    __shared__ float sqA[128], sqB[128];
    __shared__ int   labA[128], labB[128];
    __shared__ float red[256];

    const int tid = threadIdx.x;
    const int wid = tid >> 5;
    const int lid = tid & 31;
    const int rbase = bi * 128;
    const int cbase = bj * 128;

    if (tid < 128) {
        sqA[tid] = g_sq[rbase + tid];
        labA[tid] = lab[rbase + tid];
    } else {
        int t = tid - 128;
        sqB[t] = g_sq[cbase + t];
        labB[t] = lab[cbase + t];
    }

    // global->smem coords: 2 x 16B vectors per matrix per stage per thread
    const int v0 = tid;            // 0..255
    const int v1 = tid + 256;      // 256..511
    const int gr0 = v0 >> 2, gc0 = (v0 & 3) * 8;
    const int gr1 = v1 >> 2, gc1 = (v1 & 3) * 8;
    const __nv_bfloat16* Arow = g_hi + (size_t)rbase * d;
    const __nv_bfloat16* Brow = g_hi + (size_t)cbase * d;

    const int NC = d / 32;   // 24

    // prologue: issue stages 0..STAGES-2
    #pragma unroll
    for (int p = 0; p < STAGES - 1; p++) {
        const int k0 = p * 32;
        __nv_bfloat16* sA = sAbuf + p * STAGE_ELEMS;
        __nv_bfloat16* sB = sBbuf + p * STAGE_ELEMS;
        CP_ASYNC16(smem_cast(&sA[gr0 * LDS + gc0]), Arow + (size_t)gr0 * d + k0 + gc0);
        CP_ASYNC16(smem_cast(&sA[gr1 * LDS + gc1]), Arow + (size_t)gr1 * d + k0 + gc1);
        CP_ASYNC16(smem_cast(&sB[gr0 * LDS + gc0]), Brow + (size_t)gr0 * d + k0 + gc0);
        CP_ASYNC16(smem_cast(&sB[gr1 * LDS + gc1]), Brow + (size_t)gr1 * d + k0 + gc1);
        CP_COMMIT();
    }

    // warp tile coords
    const int wm = (wid & 3) * 32;
    const int wn = (wid >> 2) * 64;
    const int lrow  = lid & 15;
    const int lcol8 = (lid >> 4) * 8;

    float acc[2][8][4];
    #pragma unroll
    for (int am = 0; am < 2; am++)
        #pragma unroll
        for (int an = 0; an < 8; an++)
            #pragma unroll
            for (int r = 0; r < 4; r++) acc[am][an][r] = 0.f;

    int sidx = 0;                 // stage being consumed
    int widx = STAGES - 1;        // stage to fill next
    for (int c = 0; c < NC; c++) {
        if (c < NC - 1) { CP_WAIT1(); } else { CP_WAIT0(); }
        __syncthreads();

        // issue load for stage c+STAGES-1 (overlaps compute below)
        if (c + STAGES - 1 < NC) {
            const int k0 = (c + STAGES - 1) * 32;
            __nv_bfloat16* sA = sAbuf + widx * STAGE_ELEMS;
            __nv_bfloat16* sB = sBbuf + widx * STAGE_ELEMS;
            CP_ASYNC16(smem_cast(&sA[gr0 * LDS + gc0]), Arow + (size_t)gr0 * d + k0 + gc0);
            CP_ASYNC16(smem_cast(&sA[gr1 * LDS + gc1]), Arow + (size_t)gr1 * d + k0 + gc1);
            CP_ASYNC16(smem_cast(&sB[gr0 * LDS + gc0]), Brow + (size_t)gr0 * d + k0 + gc0);
            CP_ASYNC16(smem_cast(&sB[gr1 * LDS + gc1]), Brow + (size_t)gr1 * d + k0 + gc1);
            CP_COMMIT();
            widx = (widx + 1 == STAGES) ? 0 : widx + 1;
        }

        const __nv_bfloat16* sA = sAbuf + sidx * STAGE_ELEMS;
        const __nv_bfloat16* sB = sBbuf + sidx * STAGE_ELEMS;
        #pragma unroll
        for (int ks = 0; ks < 2; ks++) {
            uint32_t afr[2][4];
            #pragma unroll
            for (int am = 0; am < 2; am++)
                ldmx4(afr[am], smem_cast(&sA[(wm + am * 16 + lrow) * LDS + ks * 16 + lcol8]));
            uint32_t bfr[4][4];
            #pragma unroll
            for (int p = 0; p < 4; p++)
                ldmx4(bfr[p], smem_cast(&sB[(wn + p * 16 + lrow) * LDS + ks * 16 + lcol8]));
            #pragma unroll
            for (int am = 0; am < 2; am++)
                #pragma unroll
                for (int an = 0; an < 8; an++) {
                    const int p = an >> 1, h = an & 1;
                    mma16816(acc[am][an], afr[am], bfr[p][h], bfr[p][h + 2]);
                }
        }
        sidx = (sidx + 1 == STAGES) ? 0 : sidx + 1;
    }

    // fused epilogue on C fragments
    float lsum = 0.f;
    const int r4 = lid >> 2;        // 0..7
    const int c2 = (lid & 3) * 2;   // 0,2,4,6
    #pragma unroll
    for (int am = 0; am < 2; am++) {
        #pragma unroll
        for (int an = 0; an < 8; an++) {
            #pragma unroll
            for (int r = 0; r < 4; r++) {
                const int mi = wm + am * 16 + r4 + ((r & 2) ? 8 : 0);
                const int nj = wn + an * 8 + c2 + (r & 1);
                const int gi = rbase + mi;
                const int gj = cbase + nj;
                if (gi < gj) {
                    float d2 = fmaxf(sqA[mi] + sqB[nj] - 2.f * acc[am][an][r], 0.f);
                    if (labA[mi] == labB[nj]) {
                        lsum += d2;
                    } else {
                        float h = fmaxf(MARGIN - sqrtf(d2 + EPSV), 0.f);
                        lsum += h * h;
                    }
                }
            }
        }
    }

    // deterministic block reduction
    red[tid] = lsum;
    __syncthreads();
    #pragma unroll
    for (int st = 128; st > 0; st >>= 1) {
        if (tid < st) red[tid] += red[tid + st];
        __syncthreads();
    }
    if (tid == 0) g_partials[slot] = red[0];
}

// ---------------- final deterministic reduction ----------------
__global__ void final_kernel(float* out, int nblocks, float inv_count) {
    __shared__ float red[256];
    int tid = threadIdx.x;
    float s = 0.f;
    for (int i = tid; i < nblocks; i += 256) s += g_partials[i];
    red[tid] = s;
    __syncthreads();
    #pragma unroll
    for (int k = 128; k > 0; k >>= 1) {
        if (tid < k) red[tid] += red[tid + k];
        __syncthreads();
    }
    if (tid == 0) out[0] = red[0] * inv_count;
}

extern "C" void kernel_launch(void* const* d_in, const int* in_sizes, int n_in,
                              void* d_out, int out_size) {
    const float* X  = (const float*)d_in[0];
    const int* lab  = (const int*)d_in[1];
    int n = in_sizes[1];            // 4096
    int d = in_sizes[0] / n;        // 768
    int nb = n / 128;               // 32

    conv_kernel<<<(n + 7) / 8, dim3(32, 8)>>>(X, n, d);

    const int smem_bytes = STAGES * 2 * STAGE_BYTES;   // 61440
    static int attr_done = 0;
    if (!attr_done) {
        cudaFuncSetAttribute(tile_kernel,
                             cudaFuncAttributeMaxDynamicSharedMemorySize, smem_bytes);
        attr_done = 1;
    }
    int ntri = nb * (nb + 1) / 2;   // 528
    tile_kernel<<<ntri, 256, smem_bytes>>>(lab, d, nb);

    double cnt = (double)n * (double)(n - 1) * 0.5;
    final_kernel<<<1, 256>>>((float*)d_out, ntri, (float)(1.0 / cnt));
}

// round 13
// speedup vs baseline: 4.6519x; 1.1168x over previous
#include <cuda_runtime.h>
#include <cuda_bf16.h>
#include <math.h>
#include <stdint.h>

// ContrastiveLoss N=4096, D=768. loss = mean_{i<j} [same ? d2 : hinge^2]
// d2 = |xi|^2+|xj|^2-2 xi.xj ; Gram in bf16 mma.sync, norms exact fp32.

#define MARGIN 1.0f
#define EPSV   1e-12f

__device__ float g_sq[4096];
__device__ float g_partials[1024];
__device__ __nv_bfloat16 g_hi[4096 * 768];   // bf16 copy of X

#define KC   64          // K elems per stage
#define LDSE 72          // bf16 per smem row (64 data + 8 pad) -> 144B stride
#define STAGES 2
#define STAGE_ELEMS (128 * LDSE)
#define STAGE_BYTES (STAGE_ELEMS * 2)    // 18432

__device__ __forceinline__ uint32_t smem_cast(const void* p) {
    return (uint32_t)__cvta_generic_to_shared(p);
}
#define CP_ASYNC16(dst, src) \
    asm volatile("cp.async.cg.shared.global [%0], [%1], 16;\n" :: "r"(dst), "l"(src))
#define CP_COMMIT() asm volatile("cp.async.commit_group;\n" ::: "memory")
#define CP_WAIT0()  asm volatile("cp.async.wait_group 0;\n" ::: "memory")

__device__ __forceinline__ void ldmx4(uint32_t* r, uint32_t addr) {
    asm volatile("ldmatrix.sync.aligned.m8n8.x4.shared.b16 {%0,%1,%2,%3}, [%4];\n"
                 : "=r"(r[0]), "=r"(r[1]), "=r"(r[2]), "=r"(r[3]) : "r"(addr));
}
__device__ __forceinline__ void mma16816(float* c, const uint32_t* a,
                                         uint32_t b0, uint32_t b1) {
    asm volatile(
        "mma.sync.aligned.m16n8k16.row.col.f32.bf16.bf16.f32 "
        "{%0,%1,%2,%3}, {%4,%5,%6,%7}, {%8,%9}, {%0,%1,%2,%3};\n"
        : "+f"(c[0]), "+f"(c[1]), "+f"(c[2]), "+f"(c[3])
        : "r"(a[0]), "r"(a[1]), "r"(a[2]), "r"(a[3]), "r"(b0), "r"(b1));
}

// ---------------- kernel 1: convert f32 -> bf16 + row norms ----------------
// each lane handles 8 floats per step: 2x float4 load, 1x 16B bf16 store
__global__ void conv_kernel(const float* __restrict__ X, int n, int d) {
    int row = blockIdx.x * 8 + threadIdx.y;
    if (row >= n) return;
    const float4* xr = (const float4*)(X + (size_t)row * d);
    uint4* hr = (uint4*)(g_hi + (size_t)row * d);
    float s = 0.f;
    int d8 = d >> 3;   // 96
    #pragma unroll 3
    for (int c = threadIdx.x; c < d8; c += 32) {
        float4 v0 = xr[2 * c + 0];
        float4 v1 = xr[2 * c + 1];
        s += v0.x * v0.x + v0.y * v0.y + v0.z * v0.z + v0.w * v0.w;
        s += v1.x * v1.x + v1.y * v1.y + v1.z * v1.z + v1.w * v1.w;
        __nv_bfloat162 b0(__float2bfloat16_rn(v0.x), __float2bfloat16_rn(v0.y));
        __nv_bfloat162 b1(__float2bfloat16_rn(v0.z), __float2bfloat16_rn(v0.w));
        __nv_bfloat162 b2(__float2bfloat16_rn(v1.x), __float2bfloat16_rn(v1.y));
        __nv_bfloat162 b3(__float2bfloat16_rn(v1.z), __float2bfloat16_rn(v1.w));
        uint4 o;
        o.x = *(uint32_t*)&b0; o.y = *(uint32_t*)&b1;
        o.z = *(uint32_t*)&b2; o.w = *(uint32_t*)&b3;
        hr[c] = o;
    }
    #pragma unroll
    for (int o = 16; o > 0; o >>= 1) s += __shfl_down_sync(0xffffffffu, s, o);
    if (threadIdx.x == 0) g_sq[row] = s;
}

// ---------------- kernel 2: mma.sync Gram tile + fused epilogue ----------------
// Triangular 1D grid (528). 128x128 tile, 8 warps 4(M)x2(N), warp tile 32x64.
// KC=64 per stage, 2-stage cp.async pipeline, ONE sync per iter (12 iters).
__global__ void __launch_bounds__(256, 2) tile_kernel(
    const int* __restrict__ lab, int d, int nb)
{
    // decode upper-triangle block coords from linear slot
    const int slot = blockIdx.x;
    int bi = (int)((2.f * nb + 1.f -
                    sqrtf((2.f * nb + 1.f) * (2.f * nb + 1.f) - 8.f * slot)) * 0.5f);
    while (slot >= (bi + 1) * nb - ((bi + 1) * bi) / 2) bi++;
    while (slot <  bi * nb - (bi * (bi - 1)) / 2)       bi--;
    const int bj = bi + (slot - (bi * nb - (bi * (bi - 1)) / 2));

    extern __shared__ __align__(16) __nv_bfloat16 dyn[];
    __nv_bfloat16* sAbuf = dyn;                          // STAGES * STAGE_ELEMS
    __nv_bfloat16* sBbuf = dyn + STAGES * STAGE_ELEMS;
    __shared__ float sqA[128], sqB[128];
    __shared__ int   labA[128], labB[128];
    __shared__ float red[256];

    const int tid = threadIdx.x;
    const int wid = tid >> 5;
    const int lid = tid & 31;
    const int rbase = bi * 128;
    const int cbase = bj * 128;

    if (tid < 128) {
        sqA[tid] = g_sq[rbase + tid];
        labA[tid] = lab[rbase + tid];
    } else {
        int t = tid - 128;
        sqB[t] = g_sq[cbase + t];
        labB[t] = lab[cbase + t];
    }

    // global->smem: 128 rows x 128B per matrix per stage = 1024 x16B chunks;
    // 256 threads -> 4 chunks each per matrix
    const __nv_bfloat16* Arow = g_hi + (size_t)rbase * d;
    const __nv_bfloat16* Brow = g_hi + (size_t)cbase * d;
    int grs[4], gcs[4];
    #pragma unroll
    for (int t = 0; t < 4; t++) {
        int v = tid + t * 256;          // 0..1023
        grs[t] = v >> 3;                // row 0..127
        gcs[t] = (v & 7) * 8;           // elem offset 0..56
    }

    const int NC = d / KC;   // 12

    // prologue: stage 0
    #pragma unroll
    for (int t = 0; t < 4; t++) {
        CP_ASYNC16(smem_cast(&sAbuf[grs[t] * LDSE + gcs[t]]),
                   Arow + (size_t)grs[t] * d + gcs[t]);
        CP_ASYNC16(smem_cast(&sBbuf[grs[t] * LDSE + gcs[t]]),
                   Brow + (size_t)grs[t] * d + gcs[t]);
    }
    CP_COMMIT();

    // warp tile coords
    const int wm = (wid & 3) * 32;
    const int wn = (wid >> 2) * 64;
    const int lrow  = lid & 15;
    const int lcol8 = (lid >> 4) * 8;

    float acc[2][8][4];
    #pragma unroll
    for (int am = 0; am < 2; am++)
        #pragma unroll
        for (int an = 0; an < 8; an++)
            #pragma unroll
            for (int r = 0; r < 4; r++) acc[am][an][r] = 0.f;

    for (int c = 0; c < NC; c++) {
        const int s = c & 1;
        CP_WAIT0();            // stage c resident
        __syncthreads();       // all warps past stage c-1 compute; safe to fill s^1

        if (c + 1 < NC) {
            const int k0 = (c + 1) * KC;
            __nv_bfloat16* sA = sAbuf + (s ^ 1) * STAGE_ELEMS;
            __nv_bfloat16* sB = sBbuf + (s ^ 1) * STAGE_ELEMS;
            #pragma unroll
            for (int t = 0; t < 4; t++) {
                CP_ASYNC16(smem_cast(&sA[grs[t] * LDSE + gcs[t]]),
                           Arow + (size_t)grs[t] * d + k0 + gcs[t]);
                CP_ASYNC16(smem_cast(&sB[grs[t] * LDSE + gcs[t]]),
                           Brow + (size_t)grs[t] * d + k0 + gcs[t]);
            }
            CP_COMMIT();
        }

        const __nv_bfloat16* sA = sAbuf + s * STAGE_ELEMS;
        const __nv_bfloat16* sB = sBbuf + s * STAGE_ELEMS;
        #pragma unroll
        for (int ks = 0; ks < 4; ks++) {
            uint32_t afr[2][4];
            #pragma unroll
            for (int am = 0; am < 2; am++)
                ldmx4(afr[am], smem_cast(&sA[(wm + am * 16 + lrow) * LDSE + ks * 16 + lcol8]));
            uint32_t bfr[4][4];
            #pragma unroll
            for (int p = 0; p < 4; p++)
                ldmx4(bfr[p], smem_cast(&sB[(wn + p * 16 + lrow) * LDSE + ks * 16 + lcol8]));
            #pragma unroll
            for (int am = 0; am < 2; am++)
                #pragma unroll
                for (int an = 0; an < 8; an++) {
                    const int p = an >> 1, h = an & 1;
                    mma16816(acc[am][an], afr[am], bfr[p][h], bfr[p][h + 2]);
                }
        }
    }

    // fused epilogue on C fragments
    float lsum = 0.f;
    const int r4 = lid >> 2;        // 0..7
    const int c2 = (lid & 3) * 2;   // 0,2,4,6
    #pragma unroll
    for (int am = 0; am < 2; am++) {
        #pragma unroll
        for (int an = 0; an < 8; an++) {
            #pragma unroll
            for (int r = 0; r < 4; r++) {
                const int mi = wm + am * 16 + r4 + ((r & 2) ? 8 : 0);
                const int nj = wn + an * 8 + c2 + (r & 1);
                const int gi = rbase + mi;
                const int gj = cbase + nj;
                if (gi < gj) {
                    float d2 = fmaxf(sqA[mi] + sqB[nj] - 2.f * acc[am][an][r], 0.f);
                    if (labA[mi] == labB[nj]) {
                        lsum += d2;
                    } else {
                        float h = fmaxf(MARGIN - sqrtf(d2 + EPSV), 0.f);
                        lsum += h * h;
                    }
                }
            }
        }
    }

    // deterministic block reduction
    red[tid] = lsum;
    __syncthreads();
    #pragma unroll
    for (int st = 128; st > 0; st >>= 1) {
        if (tid < st) red[tid] += red[tid + st];
        __syncthreads();
    }
    if (tid == 0) g_partials[slot] = red[0];
}

// ---------------- final deterministic reduction ----------------
__global__ void final_kernel(float* out, int nblocks, float inv_count) {
    __shared__ float red[256];
    int tid = threadIdx.x;
    float s = 0.f;
    for (int i = tid; i < nblocks; i += 256) s += g_partials[i];
    red[tid] = s;
    __syncthreads();
    #pragma unroll
    for (int k = 128; k > 0; k >>= 1) {
        if (tid < k) red[tid] += red[tid + k];
        __syncthreads();
    }
    if (tid == 0) out[0] = red[0] * inv_count;
}

extern "C" void kernel_launch(void* const* d_in, const int* in_sizes, int n_in,
                              void* d_out, int out_size) {
    const float* X  = (const float*)d_in[0];
    const int* lab  = (const int*)d_in[1];
    int n = in_sizes[1];            // 4096
    int d = in_sizes[0] / n;        // 768
    int nb = n / 128;               // 32

    conv_kernel<<<(n + 7) / 8, dim3(32, 8)>>>(X, n, d);

    const int smem_bytes = STAGES * 2 * STAGE_BYTES;   // 73728
    static int attr_done = 0;
    if (!attr_done) {
        cudaFuncSetAttribute(tile_kernel,
                             cudaFuncAttributeMaxDynamicSharedMemorySize, smem_bytes);
        attr_done = 1;
    }
    int ntri = nb * (nb + 1) / 2;   // 528
    tile_kernel<<<ntri, 256, smem_bytes>>>(lab, d, nb);

    double cnt = (double)n * (double)(n - 1) * 0.5;
    final_kernel<<<1, 256>>>((float*)d_out, ntri, (float)(1.0 / cnt));
}

// round 16
// speedup vs baseline: 5.2670x; 1.1322x over previous
#include <cuda_runtime.h>
#include <cuda_bf16.h>
#include <math.h>
#include <stdint.h>

// ContrastiveLoss N=4096, D=768. loss = mean_{i<j} [same ? d2 : hinge^2]
// d2 = |xi|^2+|xj|^2-2 xi.xj ; Gram in bf16 mma.sync, norms exact fp32.

#define MARGIN 1.0f
#define EPSV   1e-12f

__device__ float g_sq[4096];
__device__ float g_partials[1024];
__device__ __nv_bfloat16 g_hi[4096 * 768];   // bf16 copy of X

#define KC   64                   // K elems per stage
#define ROWE 64                   // bf16 per smem row (128B, no pad; XOR swizzle)
#define STAGES 3
#define STAGE_ELEMS (128 * ROWE)  // 8192 elems = 16KB
#define STAGE_BYTES (STAGE_ELEMS * 2)

__device__ __forceinline__ uint32_t smem_cast(const void* p) {
    return (uint32_t)__cvta_generic_to_shared(p);
}
#define CP_ASYNC16(dst, src) \
    asm volatile("cp.async.cg.shared.global [%0], [%1], 16;\n" :: "r"(dst), "l"(src))
#define CP_COMMIT() asm volatile("cp.async.commit_group;\n" ::: "memory")
#define CP_WAIT1()  asm volatile("cp.async.wait_group 1;\n" ::: "memory")
#define CP_WAIT0()  asm volatile("cp.async.wait_group 0;\n" ::: "memory")

__device__ __forceinline__ void ldmx4(uint32_t* r, uint32_t addr) {
    asm volatile("ldmatrix.sync.aligned.m8n8.x4.shared.b16 {%0,%1,%2,%3}, [%4];\n"
                 : "=r"(r[0]), "=r"(r[1]), "=r"(r[2]), "=r"(r[3]) : "r"(addr));
}
__device__ __forceinline__ void mma16816(float* c, const uint32_t* a,
                                         uint32_t b0, uint32_t b1) {
    asm volatile(
        "mma.sync.aligned.m16n8k16.row.col.f32.bf16.bf16.f32 "
        "{%0,%1,%2,%3}, {%4,%5,%6,%7}, {%8,%9}, {%0,%1,%2,%3};\n"
        : "+f"(c[0]), "+f"(c[1]), "+f"(c[2]), "+f"(c[3])
        : "r"(a[0]), "r"(a[1]), "r"(a[2]), "r"(a[3]), "r"(b0), "r"(b1));
}

// ---------------- kernel 1: convert f32 -> bf16 + row norms ----------------
__global__ void conv_kernel(const float* __restrict__ X, int n, int d) {
    int row = blockIdx.x * 8 + threadIdx.y;
    if (row >= n) return;
    const float4* xr = (const float4*)(X + (size_t)row * d);
    uint4* hr = (uint4*)(g_hi + (size_t)row * d);
    float s = 0.f;
    int d8 = d >> 3;   // 96
    #pragma unroll 3
    for (int c = threadIdx.x; c < d8; c += 32) {
        float4 v0 = xr[2 * c + 0];
        float4 v1 = xr[2 * c + 1];
        s += v0.x * v0.x + v0.y * v0.y + v0.z * v0.z + v0.w * v0.w;
        s += v1.x * v1.x + v1.y * v1.y + v1.z * v1.z + v1.w * v1.w;
        __nv_bfloat162 b0(__float2bfloat16_rn(v0.x), __float2bfloat16_rn(v0.y));
        __nv_bfloat162 b1(__float2bfloat16_rn(v0.z), __float2bfloat16_rn(v0.w));
        __nv_bfloat162 b2(__float2bfloat16_rn(v1.x), __float2bfloat16_rn(v1.y));
        __nv_bfloat162 b3(__float2bfloat16_rn(v1.z), __float2bfloat16_rn(v1.w));
        uint4 o;
        o.x = *(uint32_t*)&b0; o.y = *(uint32_t*)&b1;
        o.z = *(uint32_t*)&b2; o.w = *(uint32_t*)&b3;
        hr[c] = o;
    }
    #pragma unroll
    for (int o = 16; o > 0; o >>= 1) s += __shfl_down_sync(0xffffffffu, s, o);
    if (threadIdx.x == 0) g_sq[row] = s;
}

// ---------------- kernel 2: mma.sync Gram tile + fused epilogue ----------------
// Triangular 1D grid (528). 128x128 tile, 8 warps 4(M)x2(N), warp tile 32x64.
// KC=64, 3-stage cp.async pipeline (prefetch distance 2), XOR-swizzled smem.
__global__ void __launch_bounds__(256, 2) tile_kernel(
    const int* __restrict__ lab, int d, int nb)
{
    // decode upper-triangle block coords from linear slot
    const int slot = blockIdx.x;
    int bi = (int)((2.f * nb + 1.f -
                    sqrtf((2.f * nb + 1.f) * (2.f * nb + 1.f) - 8.f * slot)) * 0.5f);
    while (slot >= (bi + 1) * nb - ((bi + 1) * bi) / 2) bi++;
    while (slot <  bi * nb - (bi * (bi - 1)) / 2)       bi--;
    const int bj = bi + (slot - (bi * nb - (bi * (bi - 1)) / 2));

    extern __shared__ __align__(16) __nv_bfloat16 dyn[];
    __nv_bfloat16* sAbuf = dyn;                          // STAGES * STAGE_ELEMS
    __nv_bfloat16* sBbuf = dyn + STAGES * STAGE_ELEMS;
    __shared__ float sqA[128], sqB[128];
    __shared__ int   labA[128], labB[128];
    __shared__ float red[256];

    const int tid = threadIdx.x;
    const int wid = tid >> 5;
    const int lid = tid & 31;
    const int rbase = bi * 128;
    const int cbase = bj * 128;

    if (tid < 128) {
        sqA[tid] = g_sq[rbase + tid];
        labA[tid] = lab[rbase + tid];
    } else {
        int t = tid - 128;
        sqB[t] = g_sq[cbase + t];
        labB[t] = lab[cbase + t];
    }

    // global->smem: per stage per matrix 1024 x 16B chunks; 4 per thread.
    const __nv_bfloat16* Arow = g_hi + (size_t)rbase * d;
    const __nv_bfloat16* Brow = g_hi + (size_t)cbase * d;
    int grs[4], gcl[4], sdst[4];
    #pragma unroll
    for (int t = 0; t < 4; t++) {
        int v = tid + t * 256;              // 0..1023
        int row = v >> 3;                   // 0..127
        int cl  = v & 7;                    // linear 16B chunk in row
        grs[t] = row;
        gcl[t] = cl * 8;                    // gmem elem offset
        sdst[t] = row * ROWE + ((cl ^ (row & 7)) * 8);   // swizzled smem elem offset
    }

    const int NC = d / KC;   // 12

    // prologue: issue stages 0 and 1
    #pragma unroll
    for (int p = 0; p < STAGES - 1; p++) {
        const int k0 = p * KC;
        __nv_bfloat16* sA = sAbuf + p * STAGE_ELEMS;
        __nv_bfloat16* sB = sBbuf + p * STAGE_ELEMS;
        #pragma unroll
        for (int t = 0; t < 4; t++) {
            CP_ASYNC16(smem_cast(sA + sdst[t]), Arow + (size_t)grs[t] * d + k0 + gcl[t]);
            CP_ASYNC16(smem_cast(sB + sdst[t]), Brow + (size_t)grs[t] * d + k0 + gcl[t]);
        }
        CP_COMMIT();
    }

    // warp tile coords
    const int wm = (wid & 3) * 32;
    const int wn = (wid >> 2) * 64;
    const int lrow = lid & 15;
    const int lhi  = lid >> 4;     // 0/1 -> second 16B chunk within 32B ks block

    float acc[2][8][4];
    #pragma unroll
    for (int am = 0; am < 2; am++)
        #pragma unroll
        for (int an = 0; an < 8; an++)
            #pragma unroll
            for (int r = 0; r < 4; r++) acc[am][an][r] = 0.f;

    int sidx = 0, widx = STAGES - 1;
    for (int c = 0; c < NC; c++) {
        if (c < NC - 1) { CP_WAIT1(); } else { CP_WAIT0(); }
        __syncthreads();

        if (c + STAGES - 1 < NC) {
            const int k0 = (c + STAGES - 1) * KC;
            __nv_bfloat16* sA = sAbuf + widx * STAGE_ELEMS;
            __nv_bfloat16* sB = sBbuf + widx * STAGE_ELEMS;
            #pragma unroll
            for (int t = 0; t < 4; t++) {
                CP_ASYNC16(smem_cast(sA + sdst[t]), Arow + (size_t)grs[t] * d + k0 + gcl[t]);
                CP_ASYNC16(smem_cast(sB + sdst[t]), Brow + (size_t)grs[t] * d + k0 + gcl[t]);
            }
            CP_COMMIT();
            widx = (widx + 1 == STAGES) ? 0 : widx + 1;
        }

        const __nv_bfloat16* sA = sAbuf + sidx * STAGE_ELEMS;
        const __nv_bfloat16* sB = sBbuf + sidx * STAGE_ELEMS;
        #pragma unroll
        for (int ks = 0; ks < 4; ks++) {
            uint32_t afr[2][4];
            #pragma unroll
            for (int am = 0; am < 2; am++) {
                int row = wm + am * 16 + lrow;
                int ch  = (ks * 2 + lhi) ^ (row & 7);
                ldmx4(afr[am], smem_cast(&sA[row * ROWE + ch * 8]));
            }
            uint32_t bfr[4][4];
            #pragma unroll
            for (int p = 0; p < 4; p++) {
                int row = wn + p * 16 + lrow;
                int ch  = (ks * 2 + lhi) ^ (row & 7);
                ldmx4(bfr[p], smem_cast(&sB[row * ROWE + ch * 8]));
            }
            #pragma unroll
            for (int am = 0; am < 2; am++)
                #pragma unroll
                for (int an = 0; an < 8; an++) {
                    const int p = an >> 1, h = an & 1;
                    mma16816(acc[am][an], afr[am], bfr[p][h], bfr[p][h + 2]);
                }
        }
        sidx = (sidx + 1 == STAGES) ? 0 : sidx + 1;
    }

    // fused epilogue on C fragments
    float lsum = 0.f;
    const int r4 = lid >> 2;        // 0..7
    const int c2 = (lid & 3) * 2;   // 0,2,4,6
    #pragma unroll
    for (int am = 0; am < 2; am++) {
        #pragma unroll
        for (int an = 0; an < 8; an++) {
            #pragma unroll
            for (int r = 0; r < 4; r++) {
                const int mi = wm + am * 16 + r4 + ((r & 2) ? 8 : 0);
                const int nj = wn + an * 8 + c2 + (r & 1);
                const int gi = rbase + mi;
                const int gj = cbase + nj;
                if (gi < gj) {
                    float d2 = fmaxf(sqA[mi] + sqB[nj] - 2.f * acc[am][an][r], 0.f);
                    if (labA[mi] == labB[nj]) {
                        lsum += d2;
                    } else {
                        float h = fmaxf(MARGIN - sqrtf(d2 + EPSV), 0.f);
                        lsum += h * h;
                    }
                }
            }
        }
    }

    // deterministic block reduction
    red[tid] = lsum;
    __syncthreads();
    #pragma unroll
    for (int st = 128; st > 0; st >>= 1) {
        if (tid < st) red[tid] += red[tid + st];
        __syncthreads();
    }
    if (tid == 0) g_partials[slot] = red[0];
}

// ---------------- final deterministic reduction ----------------
__global__ void final_kernel(float* out, int nblocks, float inv_count) {
    __shared__ float red[256];
    int tid = threadIdx.x;
    float s = 0.f;
    for (int i = tid; i < nblocks; i += 256) s += g_partials[i];
    red[tid] = s;
    __syncthreads();
    #pragma unroll
    for (int k = 128; k > 0; k >>= 1) {
        if (tid < k) red[tid] += red[tid + k];
        __syncthreads();
    }
    if (tid == 0) out[0] = red[0] * inv_count;
}

extern "C" void kernel_launch(void* const* d_in, const int* in_sizes, int n_in,
                              void* d_out, int out_size) {
    const float* X  = (const float*)d_in[0];
    const int* lab  = (const int*)d_in[1];
    int n = in_sizes[1];            // 4096
    int d = in_sizes[0] / n;        // 768
    int nb = n / 128;               // 32

    conv_kernel<<<(n + 7) / 8, dim3(32, 8)>>>(X, n, d);

    const int smem_bytes = STAGES * 2 * STAGE_BYTES;   // 98304
    static int attr_done = 0;
    if (!attr_done) {
        cudaFuncSetAttribute(tile_kernel,
                             cudaFuncAttributeMaxDynamicSharedMemorySize, smem_bytes);
        attr_done = 1;
    }
    int ntri = nb * (nb + 1) / 2;   // 528
    tile_kernel<<<ntri, 256, smem_bytes>>>(lab, d, nb);

    double cnt = (double)n * (double)(n - 1) * 0.5;
    final_kernel<<<1, 256>>>((float*)d_out, ntri, (float)(1.0 / cnt));
}